// round 8
// baseline (speedup 1.0000x reference)
#include <cuda_runtime.h>
#include <float.h>

#define FFT_N 4096
#define NB    16
#define ND    128
#define NLANES (NB*ND)   // 2048 lanes
#define TOPK  8
#define NT    256

// XOR swizzle: 2-way minimum on 64-bit accesses for all three ownerships
#define SWZ(i) ((i) ^ ((((unsigned)(i)) >> 4) & 15u))

// -------- scratch (device globals: allocation-free) --------
__device__ float  g_Qt[(size_t)NLANES * FFT_N];
__device__ float  g_Kt[(size_t)NLANES * FFT_N];
__device__ float  g_Vt[(size_t)NLANES * FFT_N];
__device__ float  g_Ot[(size_t)NLANES * FFT_N];
__device__ float2 g_tw[FFT_N];   // g_tw[m] = exp(-2*pi*i*m/N)

// -------- complex helpers (packed f32x2 adds: Blackwell-only FADD2) --------
__device__ __forceinline__ float2 cadd(float2 a, float2 b) {
    float2 r;
    asm("add.rn.f32x2 %0, %1, %2;"
        : "=l"(reinterpret_cast<unsigned long long&>(r))
        : "l"(reinterpret_cast<unsigned long long&>(a)),
          "l"(reinterpret_cast<unsigned long long&>(b)));
    return r;
}
__device__ __forceinline__ float2 csub(float2 a, float2 b) {
    float2 nb = make_float2(-b.x, -b.y);
    return cadd(a, nb);
}
__device__ __forceinline__ float2 cmul(float2 a, float2 b) {
    return make_float2(fmaf(a.x, b.x, -a.y * b.y), fmaf(a.x, b.y, a.y * b.x));
}
__device__ __forceinline__ float2 cmulc(float2 a, float2 b) {  // a * conj(b)
    return make_float2(fmaf(a.x, b.x, a.y * b.y), fmaf(a.y, b.x, -a.x * b.y));
}
__device__ __forceinline__ float2 ldtw(int m) {
    const float2* p = &g_tw[m];
    return make_float2(__ldg(&p->x), __ldg(&p->y));
}

__device__ __forceinline__ void fwd4(float2& a, float2& b, float2& c, float2& d,
                                     float2 w1, float2 w2, float2 w3) {
    float2 t0 = cadd(a, c), t1 = csub(a, c);
    float2 t2 = cadd(b, d), bd = csub(b, d);
    float2 t3 = make_float2(bd.y, -bd.x);        // -i * (b - d)
    a = cadd(t0, t2);
    b = cmul(cadd(t1, t3), w1);
    c = cmul(csub(t0, t2), w2);
    d = cmul(csub(t1, t3), w3);
}
__device__ __forceinline__ void fwd4_nw(float2& a, float2& b, float2& c, float2& d) {
    float2 t0 = cadd(a, c), t1 = csub(a, c);
    float2 t2 = cadd(b, d), bd = csub(b, d);
    float2 t3 = make_float2(bd.y, -bd.x);
    a = cadd(t0, t2); b = cadd(t1, t3); c = csub(t0, t2); d = csub(t1, t3);
}
__device__ __forceinline__ void inv4(float2& a, float2& b, float2& c, float2& d,
                                     float2 w1, float2 w2, float2 w3) {
    float2 u1 = cmulc(b, w1), u2 = cmulc(c, w2), u3 = cmulc(d, w3);
    float2 s0 = cadd(a, u2), d0 = csub(a, u2);
    float2 s1 = cadd(u1, u3), d1 = csub(u1, u3);
    float2 id1 = make_float2(-d1.y, d1.x);       // +i * (u1 - u3)
    a = cadd(s0, s1); b = cadd(d0, id1); c = csub(s0, s1); d = csub(d0, id1);
}
__device__ __forceinline__ void inv4_nw(float2& a, float2& b, float2& c, float2& d) {
    float2 s0 = cadd(a, c), d0 = csub(a, c);
    float2 s1 = cadd(b, d), d1 = csub(b, d);
    float2 id1 = make_float2(-d1.y, d1.x);
    a = cadd(s0, s1); b = cadd(d0, id1); c = csub(s0, s1); d = csub(d0, id1);
}

// -------- vectorized input transpose (Q,K,V fused) + twiddle init --------
// blockIdx.y in [0,48): transpose slices; blockIdx.y == 48: twiddle table.
__global__ __launch_bounds__(NT)
void transpose_in_kernel(const float* __restrict__ Q,
                         const float* __restrict__ K,
                         const float* __restrict__ V) {
    __shared__ float tile[32 * 132];   // row pitch 132 floats (33 float4)
    int z = blockIdx.y;
    if (z == 3 * NB) {
        // twiddle init: 16 of the 128 x-blocks cover 4096 entries
        if (blockIdx.x < FFT_N / NT) {
            int i = blockIdx.x * NT + threadIdx.x;
            float s, c;
            sincospif(-2.0f * (float)i / (float)FFT_N, &s, &c);
            g_tw[i] = make_float2(c, s);
        }
        return;
    }
    int b = z & (NB - 1), sel = z >> 4;
    const float* src = (sel == 0 ? Q : sel == 1 ? K : V) + (size_t)b * FFT_N * ND;
    float*       dst = (sel == 0 ? g_Qt : sel == 1 ? g_Kt : g_Vt) + (size_t)b * FFT_N * ND;
    const int t  = threadIdx.x;
    const int s0 = blockIdx.x * 32;

    float4 v[4];
#pragma unroll
    for (int i = 0; i < 4; i++) {
        int idx = t + 256 * i, row = idx >> 5, q = idx & 31;
        v[i] = ((const float4*)src)[(size_t)(s0 + row) * (ND / 4) + q];
    }
#pragma unroll
    for (int i = 0; i < 4; i++) {
        int idx = t + 256 * i, row = idx >> 5, q = idx & 31;
        *(float4*)&tile[row * 132 + 4 * q] = v[i];
    }
    __syncthreads();

#pragma unroll
    for (int i = 0; i < 4; i++) {
        int idx = t + 256 * i;
        int d = idx >> 3, q2 = idx & 7;
        float4 o;
        o.x = tile[(4 * q2 + 0) * 132 + d];
        o.y = tile[(4 * q2 + 1) * 132 + d];
        o.z = tile[(4 * q2 + 2) * 132 + d];
        o.w = tile[(4 * q2 + 3) * 132 + d];
        *(float4*)&dst[(size_t)d * FFT_N + s0 + 4 * q2] = o;
    }
}

// -------- vectorized output transpose: [B,D,S] -> [B,S,D] --------
__global__ __launch_bounds__(NT)
void transpose_out_kernel(float* __restrict__ dst) {
    __shared__ float tile[32 * 132];   // tile[s][d], pitch 132
    const int b  = blockIdx.y;
    const int s0 = blockIdx.x * 32;
    const int t  = threadIdx.x;
    const float* src = g_Ot + (size_t)b * ND * FFT_N;

    float4 v[4];
#pragma unroll
    for (int i = 0; i < 4; i++) {
        int idx = t + 256 * i;
        int d = idx >> 3, q = idx & 7;
        v[i] = *(const float4*)&src[(size_t)d * FFT_N + s0 + 4 * q];
    }
#pragma unroll
    for (int i = 0; i < 4; i++) {
        int idx = t + 256 * i;
        int d = idx >> 3, q = idx & 7;
        tile[(4 * q + 0) * 132 + d] = v[i].x;
        tile[(4 * q + 1) * 132 + d] = v[i].y;
        tile[(4 * q + 2) * 132 + d] = v[i].z;
        tile[(4 * q + 3) * 132 + d] = v[i].w;
    }
    __syncthreads();

    float* ob = dst + ((size_t)b * FFT_N + s0) * ND;
#pragma unroll
    for (int i = 0; i < 4; i++) {
        int idx = t + 256 * i;
        int row = idx >> 5, q = idx & 31;
        float4 o = *(float4*)&tile[row * 132 + 4 * q];
        *(float4*)&ob[(size_t)row * ND + 4 * q] = o;
    }
}

// -------- main per-lane kernel: radix-4 register FFT + top-8 + aggregation --------
__global__ __launch_bounds__(NT, 4)
void autocorr_fft4_kernel(const float* __restrict__ Qt, const float* __restrict__ Kt,
                          const float* __restrict__ Vt, float* __restrict__ Ot) {
    extern __shared__ float2 Z[];                 // 4096 float2 = 32 KB, swizzled
    __shared__ float candv[64];
    __shared__ int   candi[64];
    __shared__ float s_w[TOPK];
    __shared__ int   s_tau[TOPK];

    const int t  = threadIdx.x;
    const int tm = t & 15;
    const int th = t >> 4;
    const size_t lane = blockIdx.x;
    const float* qp = Qt + lane * FFT_N;
    const float* kp = Kt + lane * FFT_N;

    float2 r[16];
#pragma unroll
    for (int j = 0; j < 16; j++)
        r[j] = make_float2(qp[t + 256 * j], kp[t + 256 * j]);

    // ===== forward pass 0 (ownership A: idx = t + 256j): Q=1024 then Q=256
#pragma unroll
    for (int c = 0; c < 4; c++) {
        float2 w1 = ldtw(t + 256 * c);
        float2 w2 = cmul(w1, w1), w3 = cmul(w2, w1);
        fwd4(r[c], r[c + 4], r[c + 8], r[c + 12], w1, w2, w3);
    }
    {
        float2 w1 = ldtw(4 * t);
        float2 w2 = cmul(w1, w1), w3 = cmul(w2, w1);
#pragma unroll
        for (int g = 0; g < 4; g++)
            fwd4(r[4 * g], r[4 * g + 1], r[4 * g + 2], r[4 * g + 3], w1, w2, w3);
    }
#pragma unroll
    for (int j = 0; j < 16; j++) Z[SWZ(t + 256 * j)] = r[j];
    __syncthreads();
#pragma unroll
    for (int j = 0; j < 16; j++) r[j] = Z[SWZ(256 * th + tm + 16 * j)];

    // ===== forward pass 1 (ownership B): Q=64 then Q=16
#pragma unroll
    for (int c = 0; c < 4; c++) {
        float2 w1 = ldtw(16 * tm + 256 * c);
        float2 w2 = cmul(w1, w1), w3 = cmul(w2, w1);
        fwd4(r[c], r[c + 4], r[c + 8], r[c + 12], w1, w2, w3);
    }
    {
        float2 w1 = ldtw(64 * tm);
        float2 w2 = cmul(w1, w1), w3 = cmul(w2, w1);
#pragma unroll
        for (int g = 0; g < 4; g++)
            fwd4(r[4 * g], r[4 * g + 1], r[4 * g + 2], r[4 * g + 3], w1, w2, w3);
    }
#pragma unroll
    for (int j = 0; j < 16; j++) Z[SWZ(256 * th + tm + 16 * j)] = r[j];
    __syncthreads();
#pragma unroll
    for (int j = 0; j < 16; j++) r[j] = Z[SWZ(16 * t + j)];

    // ===== forward pass 2 (ownership C): Q=4 then Q=1
#pragma unroll
    for (int c = 0; c < 4; c++) {
        float2 w1 = ldtw(256 * c);
        float2 w2 = cmul(w1, w1), w3 = cmul(w2, w1);
        fwd4(r[c], r[c + 4], r[c + 8], r[c + 12], w1, w2, w3);
    }
#pragma unroll
    for (int g = 0; g < 4; g++)
        fwd4_nw(r[4 * g], r[4 * g + 1], r[4 * g + 2], r[4 * g + 3]);
#pragma unroll
    for (int j = 0; j < 16; j++) Z[SWZ(16 * t + j)] = r[j];
    __syncthreads();

    // ===== FUSED spectral unpack + inverse pass 0 load (d4rev is an involution)
#pragma unroll
    for (int j = 0; j < 16; j++) {
        int pp  = 16 * t + j;
        int rb  = (int)(__brev((unsigned)pp) >> 20);
        int f   = ((rb & 0x555) << 1) | ((rb >> 1) & 0x555);
        int f2  = (FFT_N - f) & (FFT_N - 1);
        int rb2 = (int)(__brev((unsigned)f2) >> 20);
        int p2  = ((rb2 & 0x555) << 1) | ((rb2 >> 1) & 0x555);
        float2 A  = Z[SWZ(pp)];
        float2 Bv = Z[SWZ(p2)];
        float qr = 0.5f * (A.x + Bv.x);
        float qi = 0.5f * (A.y - Bv.y);
        float kr = 0.5f * (A.y + Bv.y);
        float ki = 0.5f * (Bv.x - A.x);
        r[j] = make_float2(qr * kr + qi * ki, qi * kr - qr * ki);
    }

    // ===== inverse pass 0 (ownership C): Q=1 (no tw) then Q=4
#pragma unroll
    for (int g = 0; g < 4; g++)
        inv4_nw(r[4 * g], r[4 * g + 1], r[4 * g + 2], r[4 * g + 3]);
#pragma unroll
    for (int c = 0; c < 4; c++) {
        float2 w1 = ldtw(256 * c);
        float2 w2 = cmul(w1, w1), w3 = cmul(w2, w1);
        inv4(r[c], r[c + 4], r[c + 8], r[c + 12], w1, w2, w3);
    }
    __syncthreads();   // all fused-unpack reads of Z complete before overwrite
#pragma unroll
    for (int j = 0; j < 16; j++) Z[SWZ(16 * t + j)] = r[j];
    __syncthreads();
#pragma unroll
    for (int j = 0; j < 16; j++) r[j] = Z[SWZ(256 * th + tm + 16 * j)];

    // ===== inverse pass 1 (ownership B): Q=16 then Q=64
    {
        float2 w1 = ldtw(64 * tm);
        float2 w2 = cmul(w1, w1), w3 = cmul(w2, w1);
#pragma unroll
        for (int g = 0; g < 4; g++)
            inv4(r[4 * g], r[4 * g + 1], r[4 * g + 2], r[4 * g + 3], w1, w2, w3);
    }
#pragma unroll
    for (int c = 0; c < 4; c++) {
        float2 w1 = ldtw(16 * tm + 256 * c);
        float2 w2 = cmul(w1, w1), w3 = cmul(w2, w1);
        inv4(r[c], r[c + 4], r[c + 8], r[c + 12], w1, w2, w3);
    }
#pragma unroll
    for (int j = 0; j < 16; j++) Z[SWZ(256 * th + tm + 16 * j)] = r[j];
    __syncthreads();
#pragma unroll
    for (int j = 0; j < 16; j++) r[j] = Z[SWZ(t + 256 * j)];

    // ===== inverse pass 2 (ownership A): Q=256 then Q=1024
    {
        float2 w1 = ldtw(4 * t);
        float2 w2 = cmul(w1, w1), w3 = cmul(w2, w1);
#pragma unroll
        for (int g = 0; g < 4; g++)
            inv4(r[4 * g], r[4 * g + 1], r[4 * g + 2], r[4 * g + 3], w1, w2, w3);
    }
#pragma unroll
    for (int c = 0; c < 4; c++) {
        float2 w1 = ldtw(t + 256 * c);
        float2 w2 = cmul(w1, w1), w3 = cmul(w2, w1);
        inv4(r[c], r[c + 4], r[c + 8], r[c + 12], w1, w2, w3);
    }

    // corr lives in r[j].x (unscaled; topk comparison is monotone, scale at store)
    __syncthreads();   // all Z reads complete before V overlays it

    // kick off V loads (float4) so they overlap the top-k selection below
    float* Vs = (float*)Z;
    const float4* v4 = (const float4*)(Vt + lane * FFT_N);
    float4 vreg[4];
#pragma unroll
    for (int rr = 0; rr < 4; rr++) vreg[rr] = v4[t + 256 * rr];

    // ===== per-warp top-8 (register-resident, mask r[].x in place)
    const int wid = t >> 5, lid = t & 31;
    for (int sel = 0; sel < TOPK; sel++) {
        float best = -FLT_MAX;
        int   bg   = 0x7fffffff;
#pragma unroll
        for (int j = 0; j < 16; j++) {
            if (r[j].x > best) { best = r[j].x; bg = t + 256 * j; }
        }
#pragma unroll
        for (int off = 16; off > 0; off >>= 1) {
            float ov = __shfl_down_sync(0xffffffffu, best, off);
            int   og = __shfl_down_sync(0xffffffffu, bg, off);
            if (ov > best || (ov == best && og < bg)) { best = ov; bg = og; }
        }
        best = __shfl_sync(0xffffffffu, best, 0);
        bg   = __shfl_sync(0xffffffffu, bg, 0);
        if (lid == 0) { candv[wid * 8 + sel] = best; candi[wid * 8 + sel] = bg; }
#pragma unroll
        for (int j = 0; j < 16; j++)
            if (bg == t + 256 * j) r[j].x = -FLT_MAX;
    }

    // ===== overlap: warps 1-7 park V while warp 0 merges the 64 candidates.
    // Named barrier 1 (256 participants): 224 arrives + 32 syncs.
    if (wid != 0) {
        asm volatile("bar.arrive 1, 256;" ::: "memory");
#pragma unroll
        for (int rr = 0; rr < 4; rr++) ((float4*)Vs)[t + 256 * rr] = vreg[rr];
    } else {
        asm volatile("bar.sync 1, 256;" ::: "memory");   // candv/candi now visible
        float c0 = candv[lid],      c1 = candv[32 + lid];
        int   i0 = candi[lid],      i1 = candi[32 + lid];
        for (int sel = 0; sel < TOPK; sel++) {
            float best; int bg;
            if (c0 > c1 || (c0 == c1 && i0 < i1)) { best = c0; bg = i0; }
            else                                   { best = c1; bg = i1; }
#pragma unroll
            for (int off = 16; off > 0; off >>= 1) {
                float ov = __shfl_down_sync(0xffffffffu, best, off);
                int   og = __shfl_down_sync(0xffffffffu, bg, off);
                if (ov > best || (ov == best && og < bg)) { best = ov; bg = og; }
            }
            best = __shfl_sync(0xffffffffu, best, 0);
            bg   = __shfl_sync(0xffffffffu, bg, 0);
            if (lid == 0) { s_w[sel] = best * (1.0f / (float)FFT_N); s_tau[sel] = bg; }
            if (bg == i0) c0 = -FLT_MAX;
            if (bg == i1) c1 = -FLT_MAX;
        }
#pragma unroll
        for (int rr = 0; rr < 4; rr++) ((float4*)Vs)[t + 256 * rr] = vreg[rr];
    }
    __syncthreads();   // V parked + s_w/s_tau ready

    // ===== time-delay aggregation: out[t'] = sum_k w_k * V[(t' + tau_k) & (N-1)]
    float wv[TOPK]; int dv[TOPK];
#pragma unroll
    for (int kk = 0; kk < TOPK; kk++) { wv[kk] = s_w[kk]; dv[kk] = s_tau[kk]; }
    float* outp = Ot + lane * FFT_N;
#pragma unroll 8
    for (int rr = 0; rr < 16; rr++) {
        int tp = t + 256 * rr;
        float acc = 0.0f;
#pragma unroll
        for (int kk = 0; kk < TOPK; kk++)
            acc += wv[kk] * Vs[(tp + dv[kk]) & (FFT_N - 1)];
        outp[tp] = acc;
    }
}

// -------- launch --------
extern "C" void kernel_launch(void* const* d_in, const int* in_sizes, int n_in,
                              void* d_out, int out_size) {
    (void)in_sizes; (void)n_in; (void)out_size;
    const float* Q = (const float*)d_in[0];
    const float* K = (const float*)d_in[1];
    const float* V = (const float*)d_in[2];
    float* out = (float*)d_out;

    float *Qt, *Kt, *Vt, *Ot;
    cudaGetSymbolAddress((void**)&Qt, g_Qt);
    cudaGetSymbolAddress((void**)&Kt, g_Kt);
    cudaGetSymbolAddress((void**)&Vt, g_Vt);
    cudaGetSymbolAddress((void**)&Ot, g_Ot);

    // transposes + twiddle init fused into one launch (y slice 48 = twiddles)
    transpose_in_kernel<<<dim3(FFT_N / 32, 3 * NB + 1), NT>>>(Q, K, V);

    autocorr_fft4_kernel<<<NLANES, NT, FFT_N * sizeof(float2)>>>(Qt, Kt, Vt, Ot);

    transpose_out_kernel<<<dim3(FFT_N / 32, NB), NT>>>(out);
}

// round 9
// speedup vs baseline: 1.0177x; 1.0177x over previous
#include <cuda_runtime.h>
#include <float.h>

#define FFT_N 4096
#define NB    16
#define ND    128
#define NLANES (NB*ND)   // 2048 lanes
#define TOPK  8
#define NT    256

// XOR swizzle: 2-way minimum on 64-bit accesses for all three ownerships
#define SWZ(i) ((i) ^ ((((unsigned)(i)) >> 4) & 15u))

// -------- scratch (device globals: allocation-free) --------
__device__ float  g_Qt[(size_t)NLANES * FFT_N];
__device__ float  g_Kt[(size_t)NLANES * FFT_N];
__device__ float  g_Vt[(size_t)NLANES * FFT_N];
__device__ float  g_Ot[(size_t)NLANES * FFT_N];
__device__ float2 g_tw[FFT_N];   // g_tw[m] = exp(-2*pi*i*m/N)

// -------- complex helpers (packed f32x2 adds: Blackwell-only FADD2) --------
__device__ __forceinline__ float2 cadd(float2 a, float2 b) {
    float2 r;
    asm("add.rn.f32x2 %0, %1, %2;"
        : "=l"(reinterpret_cast<unsigned long long&>(r))
        : "l"(reinterpret_cast<unsigned long long&>(a)),
          "l"(reinterpret_cast<unsigned long long&>(b)));
    return r;
}
__device__ __forceinline__ float2 csub(float2 a, float2 b) {
    float2 nb = make_float2(-b.x, -b.y);
    return cadd(a, nb);
}
__device__ __forceinline__ float2 cmul(float2 a, float2 b) {
    return make_float2(fmaf(a.x, b.x, -a.y * b.y), fmaf(a.x, b.y, a.y * b.x));
}
__device__ __forceinline__ float2 cmulc(float2 a, float2 b) {  // a * conj(b)
    return make_float2(fmaf(a.x, b.x, a.y * b.y), fmaf(a.y, b.x, -a.x * b.y));
}
__device__ __forceinline__ float2 ldtw(int m) {
    const float2* p = &g_tw[m];
    return make_float2(__ldg(&p->x), __ldg(&p->y));
}

__device__ __forceinline__ void fwd4(float2& a, float2& b, float2& c, float2& d,
                                     float2 w1, float2 w2, float2 w3) {
    float2 t0 = cadd(a, c), t1 = csub(a, c);
    float2 t2 = cadd(b, d), bd = csub(b, d);
    float2 t3 = make_float2(bd.y, -bd.x);        // -i * (b - d)
    a = cadd(t0, t2);
    b = cmul(cadd(t1, t3), w1);
    c = cmul(csub(t0, t2), w2);
    d = cmul(csub(t1, t3), w3);
}
__device__ __forceinline__ void fwd4_nw(float2& a, float2& b, float2& c, float2& d) {
    float2 t0 = cadd(a, c), t1 = csub(a, c);
    float2 t2 = cadd(b, d), bd = csub(b, d);
    float2 t3 = make_float2(bd.y, -bd.x);
    a = cadd(t0, t2); b = cadd(t1, t3); c = csub(t0, t2); d = csub(t1, t3);
}
__device__ __forceinline__ void inv4(float2& a, float2& b, float2& c, float2& d,
                                     float2 w1, float2 w2, float2 w3) {
    float2 u1 = cmulc(b, w1), u2 = cmulc(c, w2), u3 = cmulc(d, w3);
    float2 s0 = cadd(a, u2), d0 = csub(a, u2);
    float2 s1 = cadd(u1, u3), d1 = csub(u1, u3);
    float2 id1 = make_float2(-d1.y, d1.x);       // +i * (u1 - u3)
    a = cadd(s0, s1); b = cadd(d0, id1); c = csub(s0, s1); d = csub(d0, id1);
}
__device__ __forceinline__ void inv4_nw(float2& a, float2& b, float2& c, float2& d) {
    float2 s0 = cadd(a, c), d0 = csub(a, c);
    float2 s1 = cadd(b, d), d1 = csub(b, d);
    float2 id1 = make_float2(-d1.y, d1.x);
    a = cadd(s0, s1); b = cadd(d0, id1); c = csub(s0, s1); d = csub(d0, id1);
}

// -------- vectorized input transpose (Q,K,V fused) + twiddle init --------
// blockIdx.y in [0,48): transpose slices; blockIdx.y == 48: twiddle table.
__global__ __launch_bounds__(NT)
void transpose_in_kernel(const float* __restrict__ Q,
                         const float* __restrict__ K,
                         const float* __restrict__ V) {
    __shared__ float tile[32 * 132];   // row pitch 132 floats (33 float4)
    int z = blockIdx.y;
    if (z == 3 * NB) {
        // twiddle init: 16 of the 128 x-blocks cover 4096 entries
        if (blockIdx.x < FFT_N / NT) {
            int i = blockIdx.x * NT + threadIdx.x;
            float s, c;
            sincospif(-2.0f * (float)i / (float)FFT_N, &s, &c);
            g_tw[i] = make_float2(c, s);
        }
        return;
    }
    int b = z & (NB - 1), sel = z >> 4;
    const float* src = (sel == 0 ? Q : sel == 1 ? K : V) + (size_t)b * FFT_N * ND;
    float*       dst = (sel == 0 ? g_Qt : sel == 1 ? g_Kt : g_Vt) + (size_t)b * FFT_N * ND;
    const int t  = threadIdx.x;
    const int s0 = blockIdx.x * 32;

    float4 v[4];
#pragma unroll
    for (int i = 0; i < 4; i++) {
        int idx = t + 256 * i, row = idx >> 5, q = idx & 31;
        v[i] = ((const float4*)src)[(size_t)(s0 + row) * (ND / 4) + q];
    }
#pragma unroll
    for (int i = 0; i < 4; i++) {
        int idx = t + 256 * i, row = idx >> 5, q = idx & 31;
        *(float4*)&tile[row * 132 + 4 * q] = v[i];
    }
    __syncthreads();

#pragma unroll
    for (int i = 0; i < 4; i++) {
        int idx = t + 256 * i;
        int d = idx >> 3, q2 = idx & 7;
        float4 o;
        o.x = tile[(4 * q2 + 0) * 132 + d];
        o.y = tile[(4 * q2 + 1) * 132 + d];
        o.z = tile[(4 * q2 + 2) * 132 + d];
        o.w = tile[(4 * q2 + 3) * 132 + d];
        *(float4*)&dst[(size_t)d * FFT_N + s0 + 4 * q2] = o;
    }
}

// -------- vectorized output transpose: [B,D,S] -> [B,S,D] --------
__global__ __launch_bounds__(NT)
void transpose_out_kernel(float* __restrict__ dst) {
    __shared__ float tile[32 * 132];   // tile[s][d], pitch 132
    const int b  = blockIdx.y;
    const int s0 = blockIdx.x * 32;
    const int t  = threadIdx.x;
    const float* src = g_Ot + (size_t)b * ND * FFT_N;

    float4 v[4];
#pragma unroll
    for (int i = 0; i < 4; i++) {
        int idx = t + 256 * i;
        int d = idx >> 3, q = idx & 7;
        v[i] = *(const float4*)&src[(size_t)d * FFT_N + s0 + 4 * q];
    }
#pragma unroll
    for (int i = 0; i < 4; i++) {
        int idx = t + 256 * i;
        int d = idx >> 3, q = idx & 7;
        tile[(4 * q + 0) * 132 + d] = v[i].x;
        tile[(4 * q + 1) * 132 + d] = v[i].y;
        tile[(4 * q + 2) * 132 + d] = v[i].z;
        tile[(4 * q + 3) * 132 + d] = v[i].w;
    }
    __syncthreads();

    float* ob = dst + ((size_t)b * FFT_N + s0) * ND;
#pragma unroll
    for (int i = 0; i < 4; i++) {
        int idx = t + 256 * i;
        int row = idx >> 5, q = idx & 31;
        float4 o = *(float4*)&tile[row * 132 + 4 * q];
        *(float4*)&ob[(size_t)row * ND + 4 * q] = o;
    }
}

// -------- main per-lane kernel: radix-4 register FFT + top-8 + aggregation --------
__global__ __launch_bounds__(NT, 4)
void autocorr_fft4_kernel(const float* __restrict__ Qt, const float* __restrict__ Kt,
                          const float* __restrict__ Vt, float* __restrict__ Ot) {
    extern __shared__ float2 Z[];                 // 4096 float2 = 32 KB, swizzled
    __shared__ float candv[64];
    __shared__ int   candi[64];
    __shared__ float s_w[TOPK];
    __shared__ int   s_tau[TOPK];

    const int t  = threadIdx.x;
    const int tm = t & 15;
    const int th = t >> 4;
    const size_t lane = blockIdx.x;
    const float* qp = Qt + lane * FFT_N;
    const float* kp = Kt + lane * FFT_N;

    float2 r[16];
#pragma unroll
    for (int j = 0; j < 16; j++)
        r[j] = make_float2(qp[t + 256 * j], kp[t + 256 * j]);

    // ===== forward pass 0 (ownership A: idx = t + 256j): Q=1024 then Q=256
#pragma unroll
    for (int c = 0; c < 4; c++) {
        float2 w1 = ldtw(t + 256 * c);
        float2 w2 = cmul(w1, w1), w3 = cmul(w2, w1);
        fwd4(r[c], r[c + 4], r[c + 8], r[c + 12], w1, w2, w3);
    }
    {
        float2 w1 = ldtw(4 * t);
        float2 w2 = cmul(w1, w1), w3 = cmul(w2, w1);
#pragma unroll
        for (int g = 0; g < 4; g++)
            fwd4(r[4 * g], r[4 * g + 1], r[4 * g + 2], r[4 * g + 3], w1, w2, w3);
    }
#pragma unroll
    for (int j = 0; j < 16; j++) Z[SWZ(t + 256 * j)] = r[j];
    __syncthreads();
#pragma unroll
    for (int j = 0; j < 16; j++) r[j] = Z[SWZ(256 * th + tm + 16 * j)];

    // ===== forward pass 1 (ownership B): Q=64 then Q=16
#pragma unroll
    for (int c = 0; c < 4; c++) {
        float2 w1 = ldtw(16 * tm + 256 * c);
        float2 w2 = cmul(w1, w1), w3 = cmul(w2, w1);
        fwd4(r[c], r[c + 4], r[c + 8], r[c + 12], w1, w2, w3);
    }
    {
        float2 w1 = ldtw(64 * tm);
        float2 w2 = cmul(w1, w1), w3 = cmul(w2, w1);
#pragma unroll
        for (int g = 0; g < 4; g++)
            fwd4(r[4 * g], r[4 * g + 1], r[4 * g + 2], r[4 * g + 3], w1, w2, w3);
    }
#pragma unroll
    for (int j = 0; j < 16; j++) Z[SWZ(256 * th + tm + 16 * j)] = r[j];
    __syncthreads();
#pragma unroll
    for (int j = 0; j < 16; j++) r[j] = Z[SWZ(16 * t + j)];

    // ===== forward pass 2 (ownership C): Q=4 then Q=1
#pragma unroll
    for (int c = 0; c < 4; c++) {
        float2 w1 = ldtw(256 * c);
        float2 w2 = cmul(w1, w1), w3 = cmul(w2, w1);
        fwd4(r[c], r[c + 4], r[c + 8], r[c + 12], w1, w2, w3);
    }
#pragma unroll
    for (int g = 0; g < 4; g++)
        fwd4_nw(r[4 * g], r[4 * g + 1], r[4 * g + 2], r[4 * g + 3]);
#pragma unroll
    for (int j = 0; j < 16; j++) Z[SWZ(16 * t + j)] = r[j];
    __syncthreads();

    // ===== FUSED spectral unpack + inverse pass 0 load (d4rev is an involution)
#pragma unroll
    for (int j = 0; j < 16; j++) {
        int pp  = 16 * t + j;
        int rb  = (int)(__brev((unsigned)pp) >> 20);
        int f   = ((rb & 0x555) << 1) | ((rb >> 1) & 0x555);
        int f2  = (FFT_N - f) & (FFT_N - 1);
        int rb2 = (int)(__brev((unsigned)f2) >> 20);
        int p2  = ((rb2 & 0x555) << 1) | ((rb2 >> 1) & 0x555);
        float2 A  = Z[SWZ(pp)];
        float2 Bv = Z[SWZ(p2)];
        float qr = 0.5f * (A.x + Bv.x);
        float qi = 0.5f * (A.y - Bv.y);
        float kr = 0.5f * (A.y + Bv.y);
        float ki = 0.5f * (Bv.x - A.x);
        r[j] = make_float2(qr * kr + qi * ki, qi * kr - qr * ki);
    }

    // ===== inverse pass 0 (ownership C): Q=1 (no tw) then Q=4
#pragma unroll
    for (int g = 0; g < 4; g++)
        inv4_nw(r[4 * g], r[4 * g + 1], r[4 * g + 2], r[4 * g + 3]);
#pragma unroll
    for (int c = 0; c < 4; c++) {
        float2 w1 = ldtw(256 * c);
        float2 w2 = cmul(w1, w1), w3 = cmul(w2, w1);
        inv4(r[c], r[c + 4], r[c + 8], r[c + 12], w1, w2, w3);
    }
    __syncthreads();   // all fused-unpack reads of Z complete before overwrite
#pragma unroll
    for (int j = 0; j < 16; j++) Z[SWZ(16 * t + j)] = r[j];
    __syncthreads();
#pragma unroll
    for (int j = 0; j < 16; j++) r[j] = Z[SWZ(256 * th + tm + 16 * j)];

    // ===== inverse pass 1 (ownership B): Q=16 then Q=64
    {
        float2 w1 = ldtw(64 * tm);
        float2 w2 = cmul(w1, w1), w3 = cmul(w2, w1);
#pragma unroll
        for (int g = 0; g < 4; g++)
            inv4(r[4 * g], r[4 * g + 1], r[4 * g + 2], r[4 * g + 3], w1, w2, w3);
    }
#pragma unroll
    for (int c = 0; c < 4; c++) {
        float2 w1 = ldtw(16 * tm + 256 * c);
        float2 w2 = cmul(w1, w1), w3 = cmul(w2, w1);
        inv4(r[c], r[c + 4], r[c + 8], r[c + 12], w1, w2, w3);
    }
#pragma unroll
    for (int j = 0; j < 16; j++) Z[SWZ(256 * th + tm + 16 * j)] = r[j];
    __syncthreads();
#pragma unroll
    for (int j = 0; j < 16; j++) r[j] = Z[SWZ(t + 256 * j)];

    // ===== inverse pass 2 (ownership A): Q=256 then Q=1024
    {
        float2 w1 = ldtw(4 * t);
        float2 w2 = cmul(w1, w1), w3 = cmul(w2, w1);
#pragma unroll
        for (int g = 0; g < 4; g++)
            inv4(r[4 * g], r[4 * g + 1], r[4 * g + 2], r[4 * g + 3], w1, w2, w3);
    }
#pragma unroll
    for (int c = 0; c < 4; c++) {
        float2 w1 = ldtw(t + 256 * c);
        float2 w2 = cmul(w1, w1), w3 = cmul(w2, w1);
        inv4(r[c], r[c + 4], r[c + 8], r[c + 12], w1, w2, w3);
    }

    // corr lives in r[j].x (unscaled; topk comparison is monotone, scale at store)
    __syncthreads();   // all Z reads complete before V overlays it

    // kick off V loads (float4) so they overlap the top-k selection below
    float* Vs = (float*)Z;
    const float4* v4 = (const float4*)(Vt + lane * FFT_N);
    float4 vreg[4];
#pragma unroll
    for (int rr = 0; rr < 4; rr++) vreg[rr] = v4[t + 256 * rr];

    // ===== per-warp top-8 (register-resident, mask r[].x in place)
    const int wid = t >> 5, lid = t & 31;
    for (int sel = 0; sel < TOPK; sel++) {
        float best = -FLT_MAX;
        int   bg   = 0x7fffffff;
#pragma unroll
        for (int j = 0; j < 16; j++) {
            if (r[j].x > best) { best = r[j].x; bg = t + 256 * j; }
        }
#pragma unroll
        for (int off = 16; off > 0; off >>= 1) {
            float ov = __shfl_down_sync(0xffffffffu, best, off);
            int   og = __shfl_down_sync(0xffffffffu, bg, off);
            if (ov > best || (ov == best && og < bg)) { best = ov; bg = og; }
        }
        best = __shfl_sync(0xffffffffu, best, 0);
        bg   = __shfl_sync(0xffffffffu, bg, 0);
        if (lid == 0) { candv[wid * 8 + sel] = best; candi[wid * 8 + sel] = bg; }
#pragma unroll
        for (int j = 0; j < 16; j++)
            if (bg == t + 256 * j) r[j].x = -FLT_MAX;
    }

    // park V in smem (overlay of Z) and sync once
#pragma unroll
    for (int rr = 0; rr < 4; rr++) ((float4*)Vs)[t + 256 * rr] = vreg[rr];
    __syncthreads();

    // ===== warp 0 merges 64 candidates -> global top-8 into smem
    if (wid == 0) {
        float c0 = candv[lid],      c1 = candv[32 + lid];
        int   i0 = candi[lid],      i1 = candi[32 + lid];
        for (int sel = 0; sel < TOPK; sel++) {
            float best; int bg;
            if (c0 > c1 || (c0 == c1 && i0 < i1)) { best = c0; bg = i0; }
            else                                   { best = c1; bg = i1; }
#pragma unroll
            for (int off = 16; off > 0; off >>= 1) {
                float ov = __shfl_down_sync(0xffffffffu, best, off);
                int   og = __shfl_down_sync(0xffffffffu, bg, off);
                if (ov > best || (ov == best && og < bg)) { best = ov; bg = og; }
            }
            best = __shfl_sync(0xffffffffu, best, 0);
            bg   = __shfl_sync(0xffffffffu, bg, 0);
            if (lid == 0) { s_w[sel] = best * (1.0f / (float)FFT_N); s_tau[sel] = bg; }
            if (bg == i0) c0 = -FLT_MAX;
            if (bg == i1) c1 = -FLT_MAX;
        }
    }
    __syncthreads();

    // ===== time-delay aggregation: out[t'] = sum_k w_k * V[(t' + tau_k) & (N-1)]
    float wv[TOPK]; int dv[TOPK];
#pragma unroll
    for (int kk = 0; kk < TOPK; kk++) { wv[kk] = s_w[kk]; dv[kk] = s_tau[kk]; }
    float* outp = Ot + lane * FFT_N;
#pragma unroll 4
    for (int rr = 0; rr < 16; rr++) {
        int tp = t + 256 * rr;
        float acc = 0.0f;
#pragma unroll
        for (int kk = 0; kk < TOPK; kk++)
            acc += wv[kk] * Vs[(tp + dv[kk]) & (FFT_N - 1)];
        outp[tp] = acc;
    }
}

// -------- launch --------
extern "C" void kernel_launch(void* const* d_in, const int* in_sizes, int n_in,
                              void* d_out, int out_size) {
    (void)in_sizes; (void)n_in; (void)out_size;
    const float* Q = (const float*)d_in[0];
    const float* K = (const float*)d_in[1];
    const float* V = (const float*)d_in[2];
    float* out = (float*)d_out;

    float *Qt, *Kt, *Vt, *Ot;
    cudaGetSymbolAddress((void**)&Qt, g_Qt);
    cudaGetSymbolAddress((void**)&Kt, g_Kt);
    cudaGetSymbolAddress((void**)&Vt, g_Vt);
    cudaGetSymbolAddress((void**)&Ot, g_Ot);

    // transposes + twiddle init fused into one launch (y slice 48 = twiddles)
    transpose_in_kernel<<<dim3(FFT_N / 32, 3 * NB + 1), NT>>>(Q, K, V);

    autocorr_fft4_kernel<<<NLANES, NT, FFT_N * sizeof(float2)>>>(Qt, Kt, Vt, Ot);

    transpose_out_kernel<<<dim3(FFT_N / 32, NB), NT>>>(out);
}